// round 14
// baseline (speedup 1.0000x reference)
#include <cuda_runtime.h>
#include <cuda_bf16.h>
#include <cstdint>
#include <math.h>

#define MTOT 32768          // B * N
#define DD   512
#define BB   8
#define NTOK 4096

// ---------------- scratch (static device globals) ---------------------------
__device__ __align__(16) __nv_bfloat16 g_xh[(size_t)MTOT * 512];
__device__ __align__(16) __nv_bfloat16 g_xl[(size_t)MTOT * 512];
__device__ __align__(16) __nv_bfloat16 g_wth[1536 * 512];   // [n][k] of [Win|Wf|Wg]
__device__ __align__(16) __nv_bfloat16 g_wtl[1536 * 512];
__device__ __align__(16) __nv_bfloat16 g_woth[512 * 512];   // [n][k] of Wout
__device__ __align__(16) __nv_bfloat16 g_wotl[512 * 512];
__device__ float g_lam[(size_t)DD * MTOT];    // [d][m]
__device__ float g_u[(size_t)DD * MTOT];      // silu(z_in)  [d][m]
__device__ float g_gate[(size_t)DD * MTOT];   // [d][m]
__device__ float g_hid[(size_t)DD * MTOT];    // [d][m]
__device__ float g_scale[MTOT];
__device__ __align__(16) __nv_bfloat16 g_ah[(size_t)MTOT * 512];  // k5 A hi [m][k]
__device__ __align__(16) __nv_bfloat16 g_al[(size_t)MTOT * 512];

// ---------------- helpers ----------------------------------------------------
__device__ __forceinline__ uint32_t smem_u32(const void* p) {
    uint32_t a;
    asm("{ .reg .u64 t; cvta.to.shared.u64 t, %1; cvt.u32.u64 %0, t; }" : "=r"(a) : "l"(p));
    return a;
}
__device__ __forceinline__ void cp16(uint32_t s, const void* g) {
    asm volatile("cp.async.cg.shared.global [%0], [%1], 16;" :: "r"(s), "l"(g));
}
__device__ __forceinline__ void ldsm4(uint32_t* r, uint32_t addr) {
    asm volatile("ldmatrix.sync.aligned.m8n8.x4.shared.b16 {%0,%1,%2,%3}, [%4];"
                 : "=r"(r[0]), "=r"(r[1]), "=r"(r[2]), "=r"(r[3]) : "r"(addr));
}
__device__ __forceinline__ void mma_bf16(float* c, const uint32_t* a,
                                         uint32_t b0, uint32_t b1) {
    asm volatile("mma.sync.aligned.m16n8k16.row.col.f32.bf16.bf16.f32 "
                 "{%0,%1,%2,%3}, {%4,%5,%6,%7}, {%8,%9}, {%0,%1,%2,%3};"
                 : "+f"(c[0]), "+f"(c[1]), "+f"(c[2]), "+f"(c[3])
                 : "r"(a[0]), "r"(a[1]), "r"(a[2]), "r"(a[3]), "r"(b0), "r"(b1));
}
#define CP_COMMIT()  asm volatile("cp.async.commit_group;" ::: "memory")
#define CP_WAIT1()   asm volatile("cp.async.wait_group 1;" ::: "memory")
#define CP_WAIT0()   asm volatile("cp.async.wait_group 0;" ::: "memory")

#define STAGE_BYTES 32768
#define SMEM_BYTES  98304   // 3 stages; epilogue staging (128*132*4=67.6KB) reuses it

__device__ __forceinline__ uint32_t sw64(uint32_t off) {
    return off ^ ((off >> 3) & 0x30);
}

// ---------------- shared HMMA mainloop --------------------------------------
// Single-sync 3-stage pipeline; term-outer MMA ordering. issue() for chunk c+2
// is placed inside the ldsm->MMA dependency shadow of substep 0 so the cp.async
// issue slots don't delay tensor-pipe start after the barrier.
__device__ __forceinline__ void gemm_core(
    uint32_t sb,
    const __nv_bfloat16* __restrict__ Ah, const __nv_bfloat16* __restrict__ Al,
    const __nv_bfloat16* __restrict__ Bh, const __nv_bfloat16* __restrict__ Bl,
    int m0, int n0, float (&c)[4][4][4])
{
    const int tid = threadIdx.x, w = tid >> 5, l = tid & 31;
    const int wm = (w & 1) * 64, wn = (w >> 1) * 32;
    const int laneRow = l & 15;
    const int colsel = (l >> 4) & 1;

#pragma unroll
    for (int i = 0; i < 4; i++)
#pragma unroll
        for (int j = 0; j < 4; j++)
#pragma unroll
            for (int k = 0; k < 4; k++) c[i][j][k] = 0.f;

    // hot ldsm offsets, fully precomputed per k-sub-step (sw64 not additive in k)
    uint32_t offA[2][4], offB[2][2];
#pragma unroll
    for (int s = 0; s < 2; s++) {
        const int kb = s * 32 + colsel * 16;
#pragma unroll
        for (int i = 0; i < 4; i++) offA[s][i] = sw64((wm + 16 * i + laneRow) * 64 + kb);
#pragma unroll
        for (int j = 0; j < 2; j++) offB[s][j] = sw64((wn + 16 * j + laneRow) * 64 + kb);
    }

    auto issue = [&](int chunk, int stage) {
        const int kc = chunk * 32;
        const uint32_t st = sb + stage * STAGE_BYTES;
#pragma unroll
        for (int i = 0; i < 2; i++) {
            const int idx = tid + i * 256;          // 0..511
            const int row = idx >> 2, u = idx & 3;
            const uint32_t d = st + sw64(row * 64 + u * 16);
            const size_t ga = (size_t)(m0 + row) * 512 + kc + u * 8;
            const size_t gb = (size_t)(n0 + row) * 512 + kc + u * 8;
            cp16(d,         Ah + ga);
            cp16(d + 8192,  Al + ga);
            cp16(d + 16384, Bh + gb);
            cp16(d + 24576, Bl + gb);
        }
        CP_COMMIT();
    };

    issue(0, 0); issue(1, 1);

    for (int cidx = 0; cidx < 16; cidx++) {
        if (cidx < 15) CP_WAIT1(); else CP_WAIT0();
        __syncthreads();
        const uint32_t s0 = sb + (cidx % 3) * STAGE_BYTES;

        // ---- substep 0: ldsm first, then prefetch-issue, then MMAs ----
        uint32_t ah[4][4], al[4][4], bh[2][4], bl[2][4];
#pragma unroll
        for (int i = 0; i < 4; i++) {
            const uint32_t a0 = s0 + offA[0][i];
            ldsm4(ah[i], a0);
            ldsm4(al[i], a0 + 8192);
        }
#pragma unroll
        for (int j = 0; j < 2; j++) {
            const uint32_t b0 = s0 + offB[0][j];
            ldsm4(bh[j], b0 + 16384);
            ldsm4(bl[j], b0 + 24576);
        }
        if (cidx + 2 < 16) issue(cidx + 2, (cidx + 2) % 3);   // hides in ldsm shadow
#pragma unroll
        for (int mi = 0; mi < 4; mi++)
#pragma unroll
            for (int nj = 0; nj < 4; nj++)
                mma_bf16(c[mi][nj], ah[mi], bh[nj >> 1][nj & 1], bh[nj >> 1][2 + (nj & 1)]);
#pragma unroll
        for (int mi = 0; mi < 4; mi++)
#pragma unroll
            for (int nj = 0; nj < 4; nj++)
                mma_bf16(c[mi][nj], ah[mi], bl[nj >> 1][nj & 1], bl[nj >> 1][2 + (nj & 1)]);
#pragma unroll
        for (int mi = 0; mi < 4; mi++)
#pragma unroll
            for (int nj = 0; nj < 4; nj++)
                mma_bf16(c[mi][nj], al[mi], bh[nj >> 1][nj & 1], bh[nj >> 1][2 + (nj & 1)]);

        // ---- substep 1 ----
#pragma unroll
        for (int i = 0; i < 4; i++) {
            const uint32_t a0 = s0 + offA[1][i];
            ldsm4(ah[i], a0);
            ldsm4(al[i], a0 + 8192);
        }
#pragma unroll
        for (int j = 0; j < 2; j++) {
            const uint32_t b0 = s0 + offB[1][j];
            ldsm4(bh[j], b0 + 16384);
            ldsm4(bl[j], b0 + 24576);
        }
#pragma unroll
        for (int mi = 0; mi < 4; mi++)
#pragma unroll
            for (int nj = 0; nj < 4; nj++)
                mma_bf16(c[mi][nj], ah[mi], bh[nj >> 1][nj & 1], bh[nj >> 1][2 + (nj & 1)]);
#pragma unroll
        for (int mi = 0; mi < 4; mi++)
#pragma unroll
            for (int nj = 0; nj < 4; nj++)
                mma_bf16(c[mi][nj], ah[mi], bl[nj >> 1][nj & 1], bl[nj >> 1][2 + (nj & 1)]);
#pragma unroll
        for (int mi = 0; mi < 4; mi++)
#pragma unroll
            for (int nj = 0; nj < 4; nj++)
                mma_bf16(c[mi][nj], al[mi], bh[nj >> 1][nj & 1], bh[nj >> 1][2 + (nj & 1)]);
    }
    __syncthreads();   // stage smem is about to be reused by the epilogue
}

// ---------------- K0x: fp32 -> bf16 hi/lo split -----------------------------
__global__ void k0x(const float* __restrict__ x)
{
    const size_t i = ((size_t)blockIdx.x * 256 + threadIdx.x) * 4;
    const float4 v = *(const float4*)(x + i);
    __nv_bfloat16 h[4], l[4];
    h[0] = __float2bfloat16(v.x); l[0] = __float2bfloat16(v.x - __bfloat162float(h[0]));
    h[1] = __float2bfloat16(v.y); l[1] = __float2bfloat16(v.y - __bfloat162float(h[1]));
    h[2] = __float2bfloat16(v.z); l[2] = __float2bfloat16(v.z - __bfloat162float(h[2]));
    h[3] = __float2bfloat16(v.w); l[3] = __float2bfloat16(v.w - __bfloat162float(h[3]));
    *(uint2*)(g_xh + i) = *(uint2*)h;
    *(uint2*)(g_xl + i) = *(uint2*)l;
}

// ---------------- K0w: transpose + split weights ----------------------------
__global__ void k0w(const float* __restrict__ Win, const float* __restrict__ Wf,
                    const float* __restrict__ Wg)
{
    __shared__ float ts[32][33];
    const int n0 = blockIdx.x * 32, k0 = blockIdx.y * 32;
    const int tx = threadIdx.x, ty = threadIdx.y;
    const int sec = n0 >> 9;
    const float* W = (sec == 0) ? Win : ((sec == 1) ? Wf : Wg);
    const int nloc0 = n0 & 511;
#pragma unroll
    for (int r = 0; r < 4; r++)
        ts[ty + r * 8][tx] = W[(size_t)(k0 + ty + r * 8) * 512 + nloc0 + tx];
    __syncthreads();
#pragma unroll
    for (int r = 0; r < 4; r++) {
        const int n = n0 + ty + r * 8, k = k0 + tx;
        const float v = ts[tx][ty + r * 8];
        const __nv_bfloat16 hi = __float2bfloat16(v);
        g_wth[(size_t)n * 512 + k] = hi;
        g_wtl[(size_t)n * 512 + k] = __float2bfloat16(v - __bfloat162float(hi));
    }
}
__global__ void k0wo(const float* __restrict__ Wout)
{
    __shared__ float ts[32][33];
    const int n0 = blockIdx.x * 32, k0 = blockIdx.y * 32;
    const int tx = threadIdx.x, ty = threadIdx.y;
#pragma unroll
    for (int r = 0; r < 4; r++)
        ts[ty + r * 8][tx] = Wout[(size_t)(k0 + ty + r * 8) * 512 + n0 + tx];
    __syncthreads();
#pragma unroll
    for (int r = 0; r < 4; r++) {
        const int n = n0 + ty + r * 8, k = k0 + tx;
        const float v = ts[tx][ty + r * 8];
        const __nv_bfloat16 hi = __float2bfloat16(v);
        g_woth[(size_t)n * 512 + k] = hi;
        g_wotl[(size_t)n * 512 + k] = __float2bfloat16(v - __bfloat162float(hi));
    }
}

// ---------------- K1t: Z = x @ [Win|Wf|Wg], fused activation epilogue -------
__global__ __launch_bounds__(256, 2) void k1t(
    const float* __restrict__ b_in, const float* __restrict__ b_f,
    const float* __restrict__ b_g, const float* __restrict__ lb)
{
    extern __shared__ char smem[];
    const uint32_t sb = smem_u32(smem);
    const int tid = threadIdx.x, w = tid >> 5, l = tid & 31;
    const int n0 = blockIdx.x * 128;      // 0..1535
    const int m0 = blockIdx.y * 128;

    float c[4][4][4];
    gemm_core(sb, g_xh, g_xl, g_wth, g_wtl, m0, n0, c);

    // stage C as [n][m] (pad 132) for coalesced [d][m] global writes
    float* sf = (float*)smem;
    {
        const int wm = (w & 1) * 64, wn = (w >> 1) * 32;
        const int mB = wm + (l >> 2), nB = wn + (l & 3) * 2;
#pragma unroll
        for (int mi = 0; mi < 4; mi++)
#pragma unroll
            for (int nj = 0; nj < 4; nj++) {
                const int m = mB + 16 * mi;
                const int n = nB + 8 * nj;
                sf[n * 132 + m]           = c[mi][nj][0];
                sf[(n + 1) * 132 + m]     = c[mi][nj][1];
                sf[n * 132 + m + 8]       = c[mi][nj][2];
                sf[(n + 1) * 132 + m + 8] = c[mi][nj][3];
            }
    }
    __syncthreads();

    const int sec = n0 >> 9;
    const int d0 = n0 & 511;
    const float lbv = lb[0];
    const float* bias = (sec == 0) ? b_in : ((sec == 1) ? b_f : b_g);
    const int nl = tid >> 1;                 // local n (d) row 0..127
    const int mh = (tid & 1) * 64;           // m half
    const int d = d0 + nl;
    const float bz = bias[d];
    float* gdst = (sec == 0) ? g_u : ((sec == 1) ? g_lam : g_gate);
    float* orow = gdst + (size_t)d * MTOT + m0 + mh;
    const float* srow = sf + nl * 132 + mh;
#pragma unroll
    for (int i = 0; i < 16; i++) {
        float4 v = *(const float4*)(srow + i * 4);
        float r4[4] = {v.x + bz, v.y + bz, v.z + bz, v.w + bz};
        float o4[4];
        if (sec == 0) {
#pragma unroll
            for (int q = 0; q < 4; q++) o4[q] = r4[q] / (1.f + __expf(-r4[q]));
        } else if (sec == 1) {
#pragma unroll
            for (int q = 0; q < 4; q++) o4[q] = lbv + (1.f - lbv) / (1.f + __expf(-r4[q]));
        } else {
#pragma unroll
            for (int q = 0; q < 4; q++) o4[q] = 1.f / (1.f + __expf(-r4[q]));
        }
        *(float4*)(orow + i * 4) = make_float4(o4[0], o4[1], o4[2], o4[3]);
    }
}

// ---------------- K3: 4-direction complex gated scan ------------------------
__global__ void k3_scan(const float* __restrict__ theta)
{
    extern __shared__ float sm[];
    float* sl = sm;
    float* si = sm + 64 * 65;
    float* sh = sm + 2 * 64 * 65;
    const int d = blockIdx.x, b = blockIdx.y;
    const size_t base = (size_t)d * MTOT + (size_t)b * NTOK;
    const int t = threadIdx.x;

#pragma unroll 8
    for (int i = t; i < 4096; i += 64) {
        const int r = i >> 6, c = i & 63;
        const float lam = g_lam[base + i];
        sl[r * 65 + c] = lam;
        si[r * 65 + c] = (1.f - lam) * g_u[base + i];
        sh[r * 65 + c] = 0.f;
    }
    const float th = theta[d];
    const float cth = cosf(th), sth = sinf(th);
    __syncthreads();
    {
        const float* lrow = sl + t * 65;
        const float* irow = si + t * 65;
        float* hrow = sh + t * 65;
        float hr = 0.f, hi = 0.f;
        for (int s2 = 0; s2 < 64; s2++) {
            const float lam = lrow[s2];
            const float lc = lam * cth, ls = lam * sth;
            const float nr = lc * hr - ls * hi + irow[s2];
            hi = ls * hr + lc * hi; hr = nr;
            hrow[s2] += hr;
        }
        hr = 0.f; hi = 0.f;
        for (int s2 = 63; s2 >= 0; s2--) {
            const float lam = lrow[s2];
            const float lc = lam * cth, ls = lam * sth;
            const float nr = lc * hr - ls * hi + irow[s2];
            hi = ls * hr + lc * hi; hr = nr;
            hrow[s2] += hr;
        }
    }
    __syncthreads();
    {
        float hr = 0.f, hi = 0.f;
        for (int s2 = 0; s2 < 64; s2++) {
            const float lam = sl[s2 * 65 + t];
            const float lc = lam * cth, ls = lam * sth;
            const float nr = lc * hr - ls * hi + si[s2 * 65 + t];
            hi = ls * hr + lc * hi; hr = nr;
            sh[s2 * 65 + t] += hr;
        }
        hr = 0.f; hi = 0.f;
        for (int s2 = 63; s2 >= 0; s2--) {
            const float lam = sl[s2 * 65 + t];
            const float lc = lam * cth, ls = lam * sth;
            const float nr = lc * hr - ls * hi + si[s2 * 65 + t];
            hi = ls * hr + lc * hi; hr = nr;
            sh[s2 * 65 + t] += hr;
        }
    }
    __syncthreads();
#pragma unroll 8
    for (int i = t; i < 4096; i += 64) {
        const int r = i >> 6, c = i & 63;
        g_hid[base + i] = sh[r * 65 + c];
    }
}

// ---------------- K4: per-row RMS scale (512 thr -> 2x MLP) ------------------
__global__ __launch_bounds__(512) void k4_scale()
{
    __shared__ float4 sp[16][32];
    const int m0 = blockIdx.x * 128;
    const int w = threadIdx.x >> 5, l = threadIdx.x & 31;
    float4 acc = make_float4(0.f, 0.f, 0.f, 0.f);
    const float* p = g_hid + (size_t)(w * 32) * MTOT + m0 + l * 4;
#pragma unroll 8
    for (int d = 0; d < 32; d++) {
        const float4 v = *(const float4*)(p + (size_t)d * MTOT);
        acc.x += v.x * v.x; acc.y += v.y * v.y;
        acc.z += v.z * v.z; acc.w += v.w * v.w;
    }
    sp[w][l] = acc;
    __syncthreads();
    if (threadIdx.x < 32) {
        float4 s = sp[0][l];
#pragma unroll
        for (int w2 = 1; w2 < 16; w2++) {
            const float4 v = sp[w2][l];
            s.x += v.x; s.y += v.y; s.z += v.z; s.w += v.w;
        }
        float4 r;
        r.x = rsqrtf(s.x * (1.f / 512.f) + 1e-6f);
        r.y = rsqrtf(s.y * (1.f / 512.f) + 1e-6f);
        r.z = rsqrtf(s.z * (1.f / 512.f) + 1e-6f);
        r.w = rsqrtf(s.w * (1.f / 512.f) + 1e-6f);
        *(float4*)&g_scale[m0 + l * 4] = r;
    }
}

// ---------------- K5p: A = gate*hid*scale -> [m][k] bf16 split ---------------
// 32m x 64d tile: writes are bf16x2-packed, full 128B warp segments.
__global__ __launch_bounds__(256) void k5p()
{
    __shared__ float ts[64][33];
    const int m0 = blockIdx.x * 32, d0 = blockIdx.y * 64;
    const int tx = threadIdx.x & 31, ty = threadIdx.x >> 5;   // 32 x 8
#pragma unroll
    for (int r = 0; r < 8; r++) {
        const int dl = ty + r * 8;
        const size_t o = (size_t)(d0 + dl) * MTOT + m0 + tx;
        ts[dl][tx] = g_gate[o] * g_hid[o] * g_scale[m0 + tx];
    }
    __syncthreads();
    const int dp = threadIdx.x & 31;          // d pair index (2 d each)
    const int mb = threadIdx.x >> 5;          // m base
#pragma unroll
    for (int r = 0; r < 4; r++) {
        const int ml = mb + r * 8;
        const float v0 = ts[dp * 2][ml];
        const float v1 = ts[dp * 2 + 1][ml];
        const __nv_bfloat16 h0 = __float2bfloat16(v0);
        const __nv_bfloat16 h1 = __float2bfloat16(v1);
        const __nv_bfloat16 l0 = __float2bfloat16(v0 - __bfloat162float(h0));
        const __nv_bfloat16 l1 = __float2bfloat16(v1 - __bfloat162float(h1));
        const size_t o = (size_t)(m0 + ml) * 512 + d0 + dp * 2;
        __nv_bfloat162 hp; hp.x = h0; hp.y = h1;
        __nv_bfloat162 lp; lp.x = l0; lp.y = l1;
        *(__nv_bfloat162*)(g_ah + o) = hp;
        *(__nv_bfloat162*)(g_al + o) = lp;
    }
}

// ---------------- K5t: Y = A @ Wout + bout ----------------------------------
__global__ __launch_bounds__(256, 2) void k5t(const float* __restrict__ bout,
                                              float* __restrict__ out)
{
    extern __shared__ char smem[];
    const uint32_t sb = smem_u32(smem);
    const int tid = threadIdx.x, w = tid >> 5, l = tid & 31;
    const int n0 = blockIdx.x * 128;      // 0..511
    const int m0 = blockIdx.y * 128;

    float c[4][4][4];
    gemm_core(sb, g_ah, g_al, g_woth, g_wotl, m0, n0, c);

    // stage C as [m][n] (pad 132) for coalesced row writes
    float* sf = (float*)smem;
    {
        const int wm = (w & 1) * 64, wn = (w >> 1) * 32;
        const int mB = wm + (l >> 2), nB = wn + (l & 3) * 2;
#pragma unroll
        for (int mi = 0; mi < 4; mi++)
#pragma unroll
            for (int nj = 0; nj < 4; nj++) {
                const int m = mB + 16 * mi;
                const int n = nB + 8 * nj;
                sf[m * 132 + n]           = c[mi][nj][0];
                sf[m * 132 + n + 1]       = c[mi][nj][1];
                sf[(m + 8) * 132 + n]     = c[mi][nj][2];
                sf[(m + 8) * 132 + n + 1] = c[mi][nj][3];
            }
    }
    __syncthreads();

    const int ml = tid >> 1;
    const int nh = (tid & 1) * 64;
    const float* srow = sf + ml * 132 + nh;
    float* orow = out + (size_t)(m0 + ml) * 512 + n0 + nh;
    const float* brow = bout + n0 + nh;
#pragma unroll
    for (int i = 0; i < 16; i++) {
        float4 v = *(const float4*)(srow + i * 4);
        const float4 bo = *(const float4*)(brow + i * 4);
        *(float4*)(orow + i * 4) =
            make_float4(v.x + bo.x, v.y + bo.y, v.z + bo.z, v.w + bo.w);
    }
}

// ---------------- launch ----------------------------------------------------
extern "C" void kernel_launch(void* const* d_in, const int* in_sizes, int n_in,
                              void* d_out, int out_size)
{
    const float* x    = (const float*)d_in[0];
    const float* lb   = (const float*)d_in[1];
    const float* Win  = (const float*)d_in[2];
    const float* bin  = (const float*)d_in[3];
    const float* Wf   = (const float*)d_in[4];
    const float* bf   = (const float*)d_in[5];
    const float* th   = (const float*)d_in[6];
    const float* Wg   = (const float*)d_in[7];
    const float* bg   = (const float*)d_in[8];
    const float* Wout = (const float*)d_in[9];
    const float* bout = (const float*)d_in[10];
    float* out = (float*)d_out;

    cudaFuncSetAttribute(k1t, cudaFuncAttributeMaxDynamicSharedMemorySize, SMEM_BYTES);
    cudaFuncSetAttribute(k5t, cudaFuncAttributeMaxDynamicSharedMemorySize, SMEM_BYTES);
    const int scan_smem = 3 * 64 * 65 * 4;
    cudaFuncSetAttribute(k3_scan, cudaFuncAttributeMaxDynamicSharedMemorySize, scan_smem);

    k0x<<<16384, 256>>>(x);
    k0w<<<dim3(48, 16), dim3(32, 8)>>>(Win, Wf, Wg);
    k0wo<<<dim3(16, 16), dim3(32, 8)>>>(Wout);

    k1t<<<dim3(12, 256), 256, SMEM_BYTES>>>(bin, bf, bg, lb);

    k3_scan<<<dim3(DD, BB), 64, scan_smem>>>(th);
    k4_scale<<<256, 512>>>();
    k5p<<<dim3(MTOT / 32, DD / 64), 256>>>();

    k5t<<<dim3(4, 256), 256, SMEM_BYTES>>>(bout, out);
}

// round 15
// speedup vs baseline: 1.1867x; 1.1867x over previous
#include <cuda_runtime.h>
#include <cuda_bf16.h>
#include <cstdint>
#include <math.h>

#define MTOT 32768          // B * N
#define DD   512
#define BB   8
#define NTOK 4096

// ---------------- scratch (static device globals) ---------------------------
__device__ __align__(16) __nv_bfloat16 g_xh[(size_t)MTOT * 512];
__device__ __align__(16) __nv_bfloat16 g_xl[(size_t)MTOT * 512];
__device__ __align__(16) __nv_bfloat16 g_wth[1536 * 512];   // [n][k] of [Win|Wf|Wg]
__device__ __align__(16) __nv_bfloat16 g_wtl[1536 * 512];
__device__ __align__(16) __nv_bfloat16 g_woth[512 * 512];   // [n][k] of Wout
__device__ __align__(16) __nv_bfloat16 g_wotl[512 * 512];
__device__ float g_lam[(size_t)DD * MTOT];    // [d][m]
__device__ float g_u[(size_t)DD * MTOT];      // silu(z_in)  [d][m]
__device__ float g_gate[(size_t)DD * MTOT];   // [d][m]
__device__ float g_hid[(size_t)DD * MTOT];    // [d][m]
__device__ float g_scale[MTOT];
__device__ __align__(16) __nv_bfloat16 g_ah[(size_t)MTOT * 512];  // k5 A hi [m][k]
__device__ __align__(16) __nv_bfloat16 g_al[(size_t)MTOT * 512];

// ---------------- helpers ----------------------------------------------------
__device__ __forceinline__ uint32_t smem_u32(const void* p) {
    uint32_t a;
    asm("{ .reg .u64 t; cvta.to.shared.u64 t, %1; cvt.u32.u64 %0, t; }" : "=r"(a) : "l"(p));
    return a;
}
__device__ __forceinline__ void cp16(uint32_t s, const void* g) {
    asm volatile("cp.async.cg.shared.global [%0], [%1], 16;" :: "r"(s), "l"(g));
}
__device__ __forceinline__ void ldsm4(uint32_t* r, uint32_t addr) {
    asm volatile("ldmatrix.sync.aligned.m8n8.x4.shared.b16 {%0,%1,%2,%3}, [%4];"
                 : "=r"(r[0]), "=r"(r[1]), "=r"(r[2]), "=r"(r[3]) : "r"(addr));
}
__device__ __forceinline__ void mma_bf16(float* c, const uint32_t* a,
                                         uint32_t b0, uint32_t b1) {
    asm volatile("mma.sync.aligned.m16n8k16.row.col.f32.bf16.bf16.f32 "
                 "{%0,%1,%2,%3}, {%4,%5,%6,%7}, {%8,%9}, {%0,%1,%2,%3};"
                 : "+f"(c[0]), "+f"(c[1]), "+f"(c[2]), "+f"(c[3])
                 : "r"(a[0]), "r"(a[1]), "r"(a[2]), "r"(a[3]), "r"(b0), "r"(b1));
}
#define CP_COMMIT()  asm volatile("cp.async.commit_group;" ::: "memory")
#define CP_WAIT1()   asm volatile("cp.async.wait_group 1;" ::: "memory")
#define CP_WAIT0()   asm volatile("cp.async.wait_group 0;" ::: "memory")

#define STAGE_BYTES 32768
#define SMEM_BYTES  98304   // 3 stages; epilogue staging (128*132*4=67.6KB) reuses it

__device__ __forceinline__ uint32_t sw64(uint32_t off) {
    return off ^ ((off >> 3) & 0x30);
}

// ---------------- shared HMMA mainloop (R12 plateau form — do not touch) ----
__device__ __forceinline__ void gemm_core(
    uint32_t sb,
    const __nv_bfloat16* __restrict__ Ah, const __nv_bfloat16* __restrict__ Al,
    const __nv_bfloat16* __restrict__ Bh, const __nv_bfloat16* __restrict__ Bl,
    int m0, int n0, float (&c)[4][4][4])
{
    const int tid = threadIdx.x, w = tid >> 5, l = tid & 31;
    const int wm = (w & 1) * 64, wn = (w >> 1) * 32;
    const int laneRow = l & 15;
    const int colsel = (l >> 4) & 1;

#pragma unroll
    for (int i = 0; i < 4; i++)
#pragma unroll
        for (int j = 0; j < 4; j++)
#pragma unroll
            for (int k = 0; k < 4; k++) c[i][j][k] = 0.f;

    // hot ldsm offsets, fully precomputed per k-sub-step (sw64 not additive in k)
    uint32_t offA[2][4], offB[2][2];
#pragma unroll
    for (int s = 0; s < 2; s++) {
        const int kb = s * 32 + colsel * 16;
#pragma unroll
        for (int i = 0; i < 4; i++) offA[s][i] = sw64((wm + 16 * i + laneRow) * 64 + kb);
#pragma unroll
        for (int j = 0; j < 2; j++) offB[s][j] = sw64((wn + 16 * j + laneRow) * 64 + kb);
    }

    auto issue = [&](int chunk, int stage) {
        const int kc = chunk * 32;
        const uint32_t s0 = sb + stage * STAGE_BYTES;
#pragma unroll
        for (int i = 0; i < 2; i++) {
            const int idx = tid + i * 256;          // 0..511
            const int row = idx >> 2, u = idx & 3;
            const uint32_t d = s0 + sw64(row * 64 + u * 16);
            const size_t ga = (size_t)(m0 + row) * 512 + kc + u * 8;
            const size_t gb = (size_t)(n0 + row) * 512 + kc + u * 8;
            cp16(d,         Ah + ga);
            cp16(d + 8192,  Al + ga);
            cp16(d + 16384, Bh + gb);
            cp16(d + 24576, Bl + gb);
        }
        CP_COMMIT();
    };

    issue(0, 0); issue(1, 1);

    for (int cidx = 0; cidx < 16; cidx++) {
        if (cidx < 15) CP_WAIT1(); else CP_WAIT0();
        __syncthreads();
        if (cidx + 2 < 16) issue(cidx + 2, (cidx + 2) % 3);
        const uint32_t s0 = sb + (cidx % 3) * STAGE_BYTES;
#pragma unroll
        for (int s = 0; s < 2; s++) {
            uint32_t ah[4][4], al[4][4], bh[2][4], bl[2][4];
#pragma unroll
            for (int i = 0; i < 4; i++) {
                const uint32_t a0 = s0 + offA[s][i];
                ldsm4(ah[i], a0);
                ldsm4(al[i], a0 + 8192);
            }
#pragma unroll
            for (int j = 0; j < 2; j++) {
                const uint32_t b0 = s0 + offB[s][j];
                ldsm4(bh[j], b0 + 16384);
                ldsm4(bl[j], b0 + 24576);
            }
            // B fragment = {same-n kLo, same-n kHi} -> {r[h], r[2+h]}
            // term-outer: 16 independent MMAs per term, no accumulator RAW chains
#pragma unroll
            for (int mi = 0; mi < 4; mi++)
#pragma unroll
                for (int nj = 0; nj < 4; nj++)
                    mma_bf16(c[mi][nj], ah[mi], bh[nj >> 1][nj & 1], bh[nj >> 1][2 + (nj & 1)]);
#pragma unroll
            for (int mi = 0; mi < 4; mi++)
#pragma unroll
                for (int nj = 0; nj < 4; nj++)
                    mma_bf16(c[mi][nj], ah[mi], bl[nj >> 1][nj & 1], bl[nj >> 1][2 + (nj & 1)]);
#pragma unroll
            for (int mi = 0; mi < 4; mi++)
#pragma unroll
                for (int nj = 0; nj < 4; nj++)
                    mma_bf16(c[mi][nj], al[mi], bh[nj >> 1][nj & 1], bh[nj >> 1][2 + (nj & 1)]);
        }
    }
    __syncthreads();   // stage smem is about to be reused by the epilogue
}

// ---------------- K0x: fp32 -> bf16 hi/lo split -----------------------------
__global__ void k0x(const float* __restrict__ x)
{
    const size_t i = ((size_t)blockIdx.x * 256 + threadIdx.x) * 4;
    const float4 v = *(const float4*)(x + i);
    __nv_bfloat16 h[4], l[4];
    h[0] = __float2bfloat16(v.x); l[0] = __float2bfloat16(v.x - __bfloat162float(h[0]));
    h[1] = __float2bfloat16(v.y); l[1] = __float2bfloat16(v.y - __bfloat162float(h[1]));
    h[2] = __float2bfloat16(v.z); l[2] = __float2bfloat16(v.z - __bfloat162float(h[2]));
    h[3] = __float2bfloat16(v.w); l[3] = __float2bfloat16(v.w - __bfloat162float(h[3]));
    *(uint2*)(g_xh + i) = *(uint2*)h;
    *(uint2*)(g_xl + i) = *(uint2*)l;
}

// ---------------- K0w: transpose + split weights ----------------------------
__global__ void k0w(const float* __restrict__ Win, const float* __restrict__ Wf,
                    const float* __restrict__ Wg)
{
    __shared__ float ts[32][33];
    const int n0 = blockIdx.x * 32, k0 = blockIdx.y * 32;
    const int tx = threadIdx.x, ty = threadIdx.y;
    const int sec = n0 >> 9;
    const float* W = (sec == 0) ? Win : ((sec == 1) ? Wf : Wg);
    const int nloc0 = n0 & 511;
#pragma unroll
    for (int r = 0; r < 4; r++)
        ts[ty + r * 8][tx] = W[(size_t)(k0 + ty + r * 8) * 512 + nloc0 + tx];
    __syncthreads();
#pragma unroll
    for (int r = 0; r < 4; r++) {
        const int n = n0 + ty + r * 8, k = k0 + tx;
        const float v = ts[tx][ty + r * 8];
        const __nv_bfloat16 hi = __float2bfloat16(v);
        g_wth[(size_t)n * 512 + k] = hi;
        g_wtl[(size_t)n * 512 + k] = __float2bfloat16(v - __bfloat162float(hi));
    }
}
__global__ void k0wo(const float* __restrict__ Wout)
{
    __shared__ float ts[32][33];
    const int n0 = blockIdx.x * 32, k0 = blockIdx.y * 32;
    const int tx = threadIdx.x, ty = threadIdx.y;
#pragma unroll
    for (int r = 0; r < 4; r++)
        ts[ty + r * 8][tx] = Wout[(size_t)(k0 + ty + r * 8) * 512 + n0 + tx];
    __syncthreads();
#pragma unroll
    for (int r = 0; r < 4; r++) {
        const int n = n0 + ty + r * 8, k = k0 + tx;
        const float v = ts[tx][ty + r * 8];
        const __nv_bfloat16 hi = __float2bfloat16(v);
        g_woth[(size_t)n * 512 + k] = hi;
        g_wotl[(size_t)n * 512 + k] = __float2bfloat16(v - __bfloat162float(hi));
    }
}

// ---------------- K1t: Z = x @ [Win|Wf|Wg], fused activation epilogue -------
__global__ __launch_bounds__(256, 2) void k1t(
    const float* __restrict__ b_in, const float* __restrict__ b_f,
    const float* __restrict__ b_g, const float* __restrict__ lb)
{
    extern __shared__ char smem[];
    const uint32_t sb = smem_u32(smem);
    const int tid = threadIdx.x, w = tid >> 5, l = tid & 31;
    const int n0 = blockIdx.x * 128;      // 0..1535
    const int m0 = blockIdx.y * 128;

    float c[4][4][4];
    gemm_core(sb, g_xh, g_xl, g_wth, g_wtl, m0, n0, c);

    // stage C as [n][m] (pad 132) for coalesced [d][m] global writes
    float* sf = (float*)smem;
    {
        const int wm = (w & 1) * 64, wn = (w >> 1) * 32;
        const int mB = wm + (l >> 2), nB = wn + (l & 3) * 2;
#pragma unroll
        for (int mi = 0; mi < 4; mi++)
#pragma unroll
            for (int nj = 0; nj < 4; nj++) {
                const int m = mB + 16 * mi;
                const int n = nB + 8 * nj;
                sf[n * 132 + m]           = c[mi][nj][0];
                sf[(n + 1) * 132 + m]     = c[mi][nj][1];
                sf[n * 132 + m + 8]       = c[mi][nj][2];
                sf[(n + 1) * 132 + m + 8] = c[mi][nj][3];
            }
    }
    __syncthreads();

    const int sec = n0 >> 9;
    const int d0 = n0 & 511;
    const float lbv = lb[0];
    const float* bias = (sec == 0) ? b_in : ((sec == 1) ? b_f : b_g);
    const int nl = tid >> 1;                 // local n (d) row 0..127
    const int mh = (tid & 1) * 64;           // m half
    const int d = d0 + nl;
    const float bz = bias[d];
    float* gdst = (sec == 0) ? g_u : ((sec == 1) ? g_lam : g_gate);
    float* orow = gdst + (size_t)d * MTOT + m0 + mh;
    const float* srow = sf + nl * 132 + mh;
#pragma unroll
    for (int i = 0; i < 16; i++) {
        float4 v = *(const float4*)(srow + i * 4);
        float r4[4] = {v.x + bz, v.y + bz, v.z + bz, v.w + bz};
        float o4[4];
        if (sec == 0) {
#pragma unroll
            for (int q = 0; q < 4; q++) o4[q] = r4[q] / (1.f + __expf(-r4[q]));
        } else if (sec == 1) {
#pragma unroll
            for (int q = 0; q < 4; q++) o4[q] = lbv + (1.f - lbv) / (1.f + __expf(-r4[q]));
        } else {
#pragma unroll
            for (int q = 0; q < 4; q++) o4[q] = 1.f / (1.f + __expf(-r4[q]));
        }
        *(float4*)(orow + i * 4) = make_float4(o4[0], o4[1], o4[2], o4[3]);
    }
}

// ---------------- K3: 4-direction complex gated scan (256-thread blocks) ----
// Memory phases use all 256 threads (4x MLP vs 64); scan phases gate on tid<64.
__global__ __launch_bounds__(256) void k3_scan(const float* __restrict__ theta)
{
    extern __shared__ float sm[];
    float* sl = sm;
    float* si = sm + 64 * 65;
    float* sh = sm + 2 * 64 * 65;
    const int d = blockIdx.x, b = blockIdx.y;
    const size_t base = (size_t)d * MTOT + (size_t)b * NTOK;
    const int tid = threadIdx.x;
    const int t = tid & 63;

#pragma unroll 4
    for (int i = tid; i < 4096; i += 256) {
        const int r = i >> 6, c = i & 63;
        const float lam = g_lam[base + i];
        sl[r * 65 + c] = lam;
        si[r * 65 + c] = (1.f - lam) * g_u[base + i];
        sh[r * 65 + c] = 0.f;
    }
    const float th = theta[d];
    const float cth = cosf(th), sth = sinf(th);
    __syncthreads();
    if (tid < 64) {
        const float* lrow = sl + t * 65;
        const float* irow = si + t * 65;
        float* hrow = sh + t * 65;
        float hr = 0.f, hi = 0.f;
        for (int s2 = 0; s2 < 64; s2++) {
            const float lam = lrow[s2];
            const float lc = lam * cth, ls = lam * sth;
            const float nr = lc * hr - ls * hi + irow[s2];
            hi = ls * hr + lc * hi; hr = nr;
            hrow[s2] += hr;
        }
        hr = 0.f; hi = 0.f;
        for (int s2 = 63; s2 >= 0; s2--) {
            const float lam = lrow[s2];
            const float lc = lam * cth, ls = lam * sth;
            const float nr = lc * hr - ls * hi + irow[s2];
            hi = ls * hr + lc * hi; hr = nr;
            hrow[s2] += hr;
        }
    }
    __syncthreads();
    if (tid < 64) {
        float hr = 0.f, hi = 0.f;
        for (int s2 = 0; s2 < 64; s2++) {
            const float lam = sl[s2 * 65 + t];
            const float lc = lam * cth, ls = lam * sth;
            const float nr = lc * hr - ls * hi + si[s2 * 65 + t];
            hi = ls * hr + lc * hi; hr = nr;
            sh[s2 * 65 + t] += hr;
        }
        hr = 0.f; hi = 0.f;
        for (int s2 = 63; s2 >= 0; s2--) {
            const float lam = sl[s2 * 65 + t];
            const float lc = lam * cth, ls = lam * sth;
            const float nr = lc * hr - ls * hi + si[s2 * 65 + t];
            hi = ls * hr + lc * hi; hr = nr;
            sh[s2 * 65 + t] += hr;
        }
    }
    __syncthreads();
#pragma unroll 4
    for (int i = tid; i < 4096; i += 256) {
        const int r = i >> 6, c = i & 63;
        g_hid[base + i] = sh[r * 65 + c];
    }
}

// ---------------- K4: per-row RMS scale (512 thr -> 2x MLP) ------------------
__global__ __launch_bounds__(512) void k4_scale()
{
    __shared__ float4 sp[16][32];
    const int m0 = blockIdx.x * 128;
    const int w = threadIdx.x >> 5, l = threadIdx.x & 31;
    float4 acc = make_float4(0.f, 0.f, 0.f, 0.f);
    const float* p = g_hid + (size_t)(w * 32) * MTOT + m0 + l * 4;
#pragma unroll 8
    for (int d = 0; d < 32; d++) {
        const float4 v = *(const float4*)(p + (size_t)d * MTOT);
        acc.x += v.x * v.x; acc.y += v.y * v.y;
        acc.z += v.z * v.z; acc.w += v.w * v.w;
    }
    sp[w][l] = acc;
    __syncthreads();
    if (threadIdx.x < 32) {
        float4 s = sp[0][l];
#pragma unroll
        for (int w2 = 1; w2 < 16; w2++) {
            const float4 v = sp[w2][l];
            s.x += v.x; s.y += v.y; s.z += v.z; s.w += v.w;
        }
        float4 r;
        r.x = rsqrtf(s.x * (1.f / 512.f) + 1e-6f);
        r.y = rsqrtf(s.y * (1.f / 512.f) + 1e-6f);
        r.z = rsqrtf(s.z * (1.f / 512.f) + 1e-6f);
        r.w = rsqrtf(s.w * (1.f / 512.f) + 1e-6f);
        *(float4*)&g_scale[m0 + l * 4] = r;
    }
}

// ---------------- K5p: A = gate*hid*scale -> [m][k] bf16 split ---------------
// 32m x 64d tile: writes are bf16x2-packed, full 128B warp segments.
__global__ __launch_bounds__(256) void k5p()
{
    __shared__ float ts[64][33];
    const int m0 = blockIdx.x * 32, d0 = blockIdx.y * 64;
    const int tx = threadIdx.x & 31, ty = threadIdx.x >> 5;   // 32 x 8
#pragma unroll
    for (int r = 0; r < 8; r++) {
        const int dl = ty + r * 8;
        const size_t o = (size_t)(d0 + dl) * MTOT + m0 + tx;
        ts[dl][tx] = g_gate[o] * g_hid[o] * g_scale[m0 + tx];
    }
    __syncthreads();
    const int dp = threadIdx.x & 31;          // d pair index (2 d each)
    const int mb = threadIdx.x >> 5;          // m base
#pragma unroll
    for (int r = 0; r < 4; r++) {
        const int ml = mb + r * 8;
        const float v0 = ts[dp * 2][ml];
        const float v1 = ts[dp * 2 + 1][ml];
        const __nv_bfloat16 h0 = __float2bfloat16(v0);
        const __nv_bfloat16 h1 = __float2bfloat16(v1);
        const __nv_bfloat16 l0 = __float2bfloat16(v0 - __bfloat162float(h0));
        const __nv_bfloat16 l1 = __float2bfloat16(v1 - __bfloat162float(h1));
        const size_t o = (size_t)(m0 + ml) * 512 + d0 + dp * 2;
        __nv_bfloat162 hp; hp.x = h0; hp.y = h1;
        __nv_bfloat162 lp; lp.x = l0; lp.y = l1;
        *(__nv_bfloat162*)(g_ah + o) = hp;
        *(__nv_bfloat162*)(g_al + o) = lp;
    }
}

// ---------------- K5t: Y = A @ Wout + bout ----------------------------------
__global__ __launch_bounds__(256, 2) void k5t(const float* __restrict__ bout,
                                              float* __restrict__ out)
{
    extern __shared__ char smem[];
    const uint32_t sb = smem_u32(smem);
    const int tid = threadIdx.x, w = tid >> 5, l = tid & 31;
    const int n0 = blockIdx.x * 128;      // 0..511
    const int m0 = blockIdx.y * 128;

    float c[4][4][4];
    gemm_core(sb, g_ah, g_al, g_woth, g_wotl, m0, n0, c);

    // stage C as [m][n] (pad 132) for coalesced row writes
    float* sf = (float*)smem;
    {
        const int wm = (w & 1) * 64, wn = (w >> 1) * 32;
        const int mB = wm + (l >> 2), nB = wn + (l & 3) * 2;
#pragma unroll
        for (int mi = 0; mi < 4; mi++)
#pragma unroll
            for (int nj = 0; nj < 4; nj++) {
                const int m = mB + 16 * mi;
                const int n = nB + 8 * nj;
                sf[m * 132 + n]           = c[mi][nj][0];
                sf[m * 132 + n + 1]       = c[mi][nj][1];
                sf[(m + 8) * 132 + n]     = c[mi][nj][2];
                sf[(m + 8) * 132 + n + 1] = c[mi][nj][3];
            }
    }
    __syncthreads();

    const int ml = tid >> 1;
    const int nh = (tid & 1) * 64;
    const float* srow = sf + ml * 132 + nh;
    float* orow = out + (size_t)(m0 + ml) * 512 + n0 + nh;
    const float* brow = bout + n0 + nh;
#pragma unroll
    for (int i = 0; i < 16; i++) {
        float4 v = *(const float4*)(srow + i * 4);
        const float4 bo = *(const float4*)(brow + i * 4);
        *(float4*)(orow + i * 4) =
            make_float4(v.x + bo.x, v.y + bo.y, v.z + bo.z, v.w + bo.w);
    }
}

// ---------------- launch ----------------------------------------------------
extern "C" void kernel_launch(void* const* d_in, const int* in_sizes, int n_in,
                              void* d_out, int out_size)
{
    const float* x    = (const float*)d_in[0];
    const float* lb   = (const float*)d_in[1];
    const float* Win  = (const float*)d_in[2];
    const float* bin  = (const float*)d_in[3];
    const float* Wf   = (const float*)d_in[4];
    const float* bf   = (const float*)d_in[5];
    const float* th   = (const float*)d_in[6];
    const float* Wg   = (const float*)d_in[7];
    const float* bg   = (const float*)d_in[8];
    const float* Wout = (const float*)d_in[9];
    const float* bout = (const float*)d_in[10];
    float* out = (float*)d_out;

    cudaFuncSetAttribute(k1t, cudaFuncAttributeMaxDynamicSharedMemorySize, SMEM_BYTES);
    cudaFuncSetAttribute(k5t, cudaFuncAttributeMaxDynamicSharedMemorySize, SMEM_BYTES);
    const int scan_smem = 3 * 64 * 65 * 4;
    cudaFuncSetAttribute(k3_scan, cudaFuncAttributeMaxDynamicSharedMemorySize, scan_smem);

    k0x<<<16384, 256>>>(x);
    k0w<<<dim3(48, 16), dim3(32, 8)>>>(Win, Wf, Wg);
    k0wo<<<dim3(16, 16), dim3(32, 8)>>>(Wout);

    k1t<<<dim3(12, 256), 256, SMEM_BYTES>>>(bin, bf, bg, lb);

    k3_scan<<<dim3(DD, BB), 256, scan_smem>>>(th);
    k4_scale<<<256, 512>>>();
    k5p<<<dim3(MTOT / 32, DD / 64), 256>>>();

    k5t<<<dim3(4, 256), 256, SMEM_BYTES>>>(bout, out);
}

// round 16
// speedup vs baseline: 1.1935x; 1.0057x over previous
#include <cuda_runtime.h>
#include <cuda_bf16.h>
#include <cstdint>
#include <math.h>

#define MTOT 32768          // B * N
#define DD   512
#define BB   8
#define NTOK 4096

// ---------------- scratch (static device globals) ---------------------------
__device__ __align__(16) __nv_bfloat16 g_xh[(size_t)MTOT * 512];
__device__ __align__(16) __nv_bfloat16 g_xl[(size_t)MTOT * 512];
__device__ __align__(16) __nv_bfloat16 g_wth[1536 * 512];   // [n][k] of [Win|Wf|Wg]
__device__ __align__(16) __nv_bfloat16 g_wtl[1536 * 512];
__device__ __align__(16) __nv_bfloat16 g_woth[512 * 512];   // [n][k] of Wout
__device__ __align__(16) __nv_bfloat16 g_wotl[512 * 512];
__device__ float g_lam[(size_t)DD * MTOT];    // [d][m]
__device__ float g_u[(size_t)DD * MTOT];      // silu(z_in)  [d][m]
__device__ float g_gate[(size_t)DD * MTOT];   // [d][m]
__device__ float g_hid[(size_t)DD * MTOT];    // [d][m]
__device__ float g_scale[MTOT];
__device__ __align__(16) __nv_bfloat16 g_ah[(size_t)MTOT * 512];  // k5 A hi [m][k]
__device__ __align__(16) __nv_bfloat16 g_al[(size_t)MTOT * 512];

// ---------------- helpers ----------------------------------------------------
__device__ __forceinline__ uint32_t smem_u32(const void* p) {
    uint32_t a;
    asm("{ .reg .u64 t; cvta.to.shared.u64 t, %1; cvt.u32.u64 %0, t; }" : "=r"(a) : "l"(p));
    return a;
}
__device__ __forceinline__ void cp16(uint32_t s, const void* g) {
    asm volatile("cp.async.cg.shared.global [%0], [%1], 16;" :: "r"(s), "l"(g));
}
__device__ __forceinline__ void ldsm4(uint32_t* r, uint32_t addr) {
    asm volatile("ldmatrix.sync.aligned.m8n8.x4.shared.b16 {%0,%1,%2,%3}, [%4];"
                 : "=r"(r[0]), "=r"(r[1]), "=r"(r[2]), "=r"(r[3]) : "r"(addr));
}
__device__ __forceinline__ void mma_bf16(float* c, const uint32_t* a,
                                         uint32_t b0, uint32_t b1) {
    asm volatile("mma.sync.aligned.m16n8k16.row.col.f32.bf16.bf16.f32 "
                 "{%0,%1,%2,%3}, {%4,%5,%6,%7}, {%8,%9}, {%0,%1,%2,%3};"
                 : "+f"(c[0]), "+f"(c[1]), "+f"(c[2]), "+f"(c[3])
                 : "r"(a[0]), "r"(a[1]), "r"(a[2]), "r"(a[3]), "r"(b0), "r"(b1));
}
#define CP_COMMIT()  asm volatile("cp.async.commit_group;" ::: "memory")
#define CP_WAIT1()   asm volatile("cp.async.wait_group 1;" ::: "memory")
#define CP_WAIT0()   asm volatile("cp.async.wait_group 0;" ::: "memory")

#define STAGE_BYTES 32768
#define SMEM_BYTES  98304   // 3 stages; epilogue staging (128*132*4=67.6KB) reuses it

__device__ __forceinline__ uint32_t sw64(uint32_t off) {
    return off ^ ((off >> 3) & 0x30);
}

// ---------------- shared HMMA mainloop (R12 plateau form — do not touch) ----
__device__ __forceinline__ void gemm_core(
    uint32_t sb,
    const __nv_bfloat16* __restrict__ Ah, const __nv_bfloat16* __restrict__ Al,
    const __nv_bfloat16* __restrict__ Bh, const __nv_bfloat16* __restrict__ Bl,
    int m0, int n0, float (&c)[4][4][4])
{
    const int tid = threadIdx.x, w = tid >> 5, l = tid & 31;
    const int wm = (w & 1) * 64, wn = (w >> 1) * 32;
    const int laneRow = l & 15;
    const int colsel = (l >> 4) & 1;

#pragma unroll
    for (int i = 0; i < 4; i++)
#pragma unroll
        for (int j = 0; j < 4; j++)
#pragma unroll
            for (int k = 0; k < 4; k++) c[i][j][k] = 0.f;

    // hot ldsm offsets, fully precomputed per k-sub-step (sw64 not additive in k)
    uint32_t offA[2][4], offB[2][2];
#pragma unroll
    for (int s = 0; s < 2; s++) {
        const int kb = s * 32 + colsel * 16;
#pragma unroll
        for (int i = 0; i < 4; i++) offA[s][i] = sw64((wm + 16 * i + laneRow) * 64 + kb);
#pragma unroll
        for (int j = 0; j < 2; j++) offB[s][j] = sw64((wn + 16 * j + laneRow) * 64 + kb);
    }

    auto issue = [&](int chunk, int stage) {
        const int kc = chunk * 32;
        const uint32_t s0 = sb + stage * STAGE_BYTES;
#pragma unroll
        for (int i = 0; i < 2; i++) {
            const int idx = tid + i * 256;          // 0..511
            const int row = idx >> 2, u = idx & 3;
            const uint32_t d = s0 + sw64(row * 64 + u * 16);
            const size_t ga = (size_t)(m0 + row) * 512 + kc + u * 8;
            const size_t gb = (size_t)(n0 + row) * 512 + kc + u * 8;
            cp16(d,         Ah + ga);
            cp16(d + 8192,  Al + ga);
            cp16(d + 16384, Bh + gb);
            cp16(d + 24576, Bl + gb);
        }
        CP_COMMIT();
    };

    issue(0, 0); issue(1, 1);

    for (int cidx = 0; cidx < 16; cidx++) {
        if (cidx < 15) CP_WAIT1(); else CP_WAIT0();
        __syncthreads();
        if (cidx + 2 < 16) issue(cidx + 2, (cidx + 2) % 3);
        const uint32_t s0 = sb + (cidx % 3) * STAGE_BYTES;
#pragma unroll
        for (int s = 0; s < 2; s++) {
            uint32_t ah[4][4], al[4][4], bh[2][4], bl[2][4];
#pragma unroll
            for (int i = 0; i < 4; i++) {
                const uint32_t a0 = s0 + offA[s][i];
                ldsm4(ah[i], a0);
                ldsm4(al[i], a0 + 8192);
            }
#pragma unroll
            for (int j = 0; j < 2; j++) {
                const uint32_t b0 = s0 + offB[s][j];
                ldsm4(bh[j], b0 + 16384);
                ldsm4(bl[j], b0 + 24576);
            }
            // B fragment = {same-n kLo, same-n kHi} -> {r[h], r[2+h]}
            // term-outer: 16 independent MMAs per term, no accumulator RAW chains
#pragma unroll
            for (int mi = 0; mi < 4; mi++)
#pragma unroll
                for (int nj = 0; nj < 4; nj++)
                    mma_bf16(c[mi][nj], ah[mi], bh[nj >> 1][nj & 1], bh[nj >> 1][2 + (nj & 1)]);
#pragma unroll
            for (int mi = 0; mi < 4; mi++)
#pragma unroll
                for (int nj = 0; nj < 4; nj++)
                    mma_bf16(c[mi][nj], ah[mi], bl[nj >> 1][nj & 1], bl[nj >> 1][2 + (nj & 1)]);
#pragma unroll
            for (int mi = 0; mi < 4; mi++)
#pragma unroll
                for (int nj = 0; nj < 4; nj++)
                    mma_bf16(c[mi][nj], al[mi], bh[nj >> 1][nj & 1], bh[nj >> 1][2 + (nj & 1)]);
        }
    }
    __syncthreads();   // stage smem is about to be reused by the epilogue
}

// ---------------- K0x: fp32 -> bf16 hi/lo split -----------------------------
__global__ void k0x(const float* __restrict__ x)
{
    const size_t i = ((size_t)blockIdx.x * 256 + threadIdx.x) * 4;
    const float4 v = *(const float4*)(x + i);
    __nv_bfloat16 h[4], l[4];
    h[0] = __float2bfloat16(v.x); l[0] = __float2bfloat16(v.x - __bfloat162float(h[0]));
    h[1] = __float2bfloat16(v.y); l[1] = __float2bfloat16(v.y - __bfloat162float(h[1]));
    h[2] = __float2bfloat16(v.z); l[2] = __float2bfloat16(v.z - __bfloat162float(h[2]));
    h[3] = __float2bfloat16(v.w); l[3] = __float2bfloat16(v.w - __bfloat162float(h[3]));
    *(uint2*)(g_xh + i) = *(uint2*)h;
    *(uint2*)(g_xl + i) = *(uint2*)l;
}

// ---------------- K0w: transpose + split weights ----------------------------
__global__ void k0w(const float* __restrict__ Win, const float* __restrict__ Wf,
                    const float* __restrict__ Wg)
{
    __shared__ float ts[32][33];
    const int n0 = blockIdx.x * 32, k0 = blockIdx.y * 32;
    const int tx = threadIdx.x, ty = threadIdx.y;
    const int sec = n0 >> 9;
    const float* W = (sec == 0) ? Win : ((sec == 1) ? Wf : Wg);
    const int nloc0 = n0 & 511;
#pragma unroll
    for (int r = 0; r < 4; r++)
        ts[ty + r * 8][tx] = W[(size_t)(k0 + ty + r * 8) * 512 + nloc0 + tx];
    __syncthreads();
#pragma unroll
    for (int r = 0; r < 4; r++) {
        const int n = n0 + ty + r * 8, k = k0 + tx;
        const float v = ts[tx][ty + r * 8];
        const __nv_bfloat16 hi = __float2bfloat16(v);
        g_wth[(size_t)n * 512 + k] = hi;
        g_wtl[(size_t)n * 512 + k] = __float2bfloat16(v - __bfloat162float(hi));
    }
}
__global__ void k0wo(const float* __restrict__ Wout)
{
    __shared__ float ts[32][33];
    const int n0 = blockIdx.x * 32, k0 = blockIdx.y * 32;
    const int tx = threadIdx.x, ty = threadIdx.y;
#pragma unroll
    for (int r = 0; r < 4; r++)
        ts[ty + r * 8][tx] = Wout[(size_t)(k0 + ty + r * 8) * 512 + n0 + tx];
    __syncthreads();
#pragma unroll
    for (int r = 0; r < 4; r++) {
        const int n = n0 + ty + r * 8, k = k0 + tx;
        const float v = ts[tx][ty + r * 8];
        const __nv_bfloat16 hi = __float2bfloat16(v);
        g_woth[(size_t)n * 512 + k] = hi;
        g_wotl[(size_t)n * 512 + k] = __float2bfloat16(v - __bfloat162float(hi));
    }
}

// ---------------- K1t: Z = x @ [Win|Wf|Wg], fused activation epilogue -------
__global__ __launch_bounds__(256, 2) void k1t(
    const float* __restrict__ b_in, const float* __restrict__ b_f,
    const float* __restrict__ b_g, const float* __restrict__ lb)
{
    extern __shared__ char smem[];
    const uint32_t sb = smem_u32(smem);
    const int tid = threadIdx.x, w = tid >> 5, l = tid & 31;
    const int n0 = blockIdx.x * 128;      // 0..1535
    const int m0 = blockIdx.y * 128;

    float c[4][4][4];
    gemm_core(sb, g_xh, g_xl, g_wth, g_wtl, m0, n0, c);

    // stage C as [n][m] (pad 132) for coalesced [d][m] global writes
    float* sf = (float*)smem;
    {
        const int wm = (w & 1) * 64, wn = (w >> 1) * 32;
        const int mB = wm + (l >> 2), nB = wn + (l & 3) * 2;
#pragma unroll
        for (int mi = 0; mi < 4; mi++)
#pragma unroll
            for (int nj = 0; nj < 4; nj++) {
                const int m = mB + 16 * mi;
                const int n = nB + 8 * nj;
                sf[n * 132 + m]           = c[mi][nj][0];
                sf[(n + 1) * 132 + m]     = c[mi][nj][1];
                sf[n * 132 + m + 8]       = c[mi][nj][2];
                sf[(n + 1) * 132 + m + 8] = c[mi][nj][3];
            }
    }
    __syncthreads();

    const int sec = n0 >> 9;
    const int d0 = n0 & 511;
    const float lbv = lb[0];
    const float* bias = (sec == 0) ? b_in : ((sec == 1) ? b_f : b_g);
    const int nl = tid >> 1;                 // local n (d) row 0..127
    const int mh = (tid & 1) * 64;           // m half
    const int d = d0 + nl;
    const float bz = bias[d];
    float* gdst = (sec == 0) ? g_u : ((sec == 1) ? g_lam : g_gate);
    float* orow = gdst + (size_t)d * MTOT + m0 + mh;
    const float* srow = sf + nl * 132 + mh;
#pragma unroll
    for (int i = 0; i < 16; i++) {
        float4 v = *(const float4*)(srow + i * 4);
        float r4[4] = {v.x + bz, v.y + bz, v.z + bz, v.w + bz};
        float o4[4];
        if (sec == 0) {
#pragma unroll
            for (int q = 0; q < 4; q++) o4[q] = r4[q] / (1.f + __expf(-r4[q]));
        } else if (sec == 1) {
#pragma unroll
            for (int q = 0; q < 4; q++) o4[q] = lbv + (1.f - lbv) / (1.f + __expf(-r4[q]));
        } else {
#pragma unroll
            for (int q = 0; q < 4; q++) o4[q] = 1.f / (1.f + __expf(-r4[q]));
        }
        *(float4*)(orow + i * 4) = make_float4(o4[0], o4[1], o4[2], o4[3]);
    }
}

// ---------------- K3: 4-direction complex gated scan (512-thread blocks) ----
// Memory phases use all 512 threads (8x MLP vs 64); scan phases gate on tid<64.
__global__ __launch_bounds__(512) void k3_scan(const float* __restrict__ theta)
{
    extern __shared__ float sm[];
    float* sl = sm;
    float* si = sm + 64 * 65;
    float* sh = sm + 2 * 64 * 65;
    const int d = blockIdx.x, b = blockIdx.y;
    const size_t base = (size_t)d * MTOT + (size_t)b * NTOK;
    const int tid = threadIdx.x;
    const int t = tid & 63;

#pragma unroll 2
    for (int i = tid; i < 4096; i += 512) {
        const int r = i >> 6, c = i & 63;
        const float lam = g_lam[base + i];
        sl[r * 65 + c] = lam;
        si[r * 65 + c] = (1.f - lam) * g_u[base + i];
        sh[r * 65 + c] = 0.f;
    }
    const float th = theta[d];
    const float cth = cosf(th), sth = sinf(th);
    __syncthreads();
    if (tid < 64) {
        const float* lrow = sl + t * 65;
        const float* irow = si + t * 65;
        float* hrow = sh + t * 65;
        float hr = 0.f, hi = 0.f;
        for (int s2 = 0; s2 < 64; s2++) {
            const float lam = lrow[s2];
            const float lc = lam * cth, ls = lam * sth;
            const float nr = lc * hr - ls * hi + irow[s2];
            hi = ls * hr + lc * hi; hr = nr;
            hrow[s2] += hr;
        }
        hr = 0.f; hi = 0.f;
        for (int s2 = 63; s2 >= 0; s2--) {
            const float lam = lrow[s2];
            const float lc = lam * cth, ls = lam * sth;
            const float nr = lc * hr - ls * hi + irow[s2];
            hi = ls * hr + lc * hi; hr = nr;
            hrow[s2] += hr;
        }
    }
    __syncthreads();
    if (tid < 64) {
        float hr = 0.f, hi = 0.f;
        for (int s2 = 0; s2 < 64; s2++) {
            const float lam = sl[s2 * 65 + t];
            const float lc = lam * cth, ls = lam * sth;
            const float nr = lc * hr - ls * hi + si[s2 * 65 + t];
            hi = ls * hr + lc * hi; hr = nr;
            sh[s2 * 65 + t] += hr;
        }
        hr = 0.f; hi = 0.f;
        for (int s2 = 63; s2 >= 0; s2--) {
            const float lam = sl[s2 * 65 + t];
            const float lc = lam * cth, ls = lam * sth;
            const float nr = lc * hr - ls * hi + si[s2 * 65 + t];
            hi = ls * hr + lc * hi; hr = nr;
            sh[s2 * 65 + t] += hr;
        }
    }
    __syncthreads();
#pragma unroll 2
    for (int i = tid; i < 4096; i += 512) {
        const int r = i >> 6, c = i & 63;
        g_hid[base + i] = sh[r * 65 + c];
    }
}

// ---------------- K4: per-row RMS scale (512 thr -> 2x MLP) ------------------
__global__ __launch_bounds__(512) void k4_scale()
{
    __shared__ float4 sp[16][32];
    const int m0 = blockIdx.x * 128;
    const int w = threadIdx.x >> 5, l = threadIdx.x & 31;
    float4 acc = make_float4(0.f, 0.f, 0.f, 0.f);
    const float* p = g_hid + (size_t)(w * 32) * MTOT + m0 + l * 4;
#pragma unroll 8
    for (int d = 0; d < 32; d++) {
        const float4 v = *(const float4*)(p + (size_t)d * MTOT);
        acc.x += v.x * v.x; acc.y += v.y * v.y;
        acc.z += v.z * v.z; acc.w += v.w * v.w;
    }
    sp[w][l] = acc;
    __syncthreads();
    if (threadIdx.x < 32) {
        float4 s = sp[0][l];
#pragma unroll
        for (int w2 = 1; w2 < 16; w2++) {
            const float4 v = sp[w2][l];
            s.x += v.x; s.y += v.y; s.z += v.z; s.w += v.w;
        }
        float4 r;
        r.x = rsqrtf(s.x * (1.f / 512.f) + 1e-6f);
        r.y = rsqrtf(s.y * (1.f / 512.f) + 1e-6f);
        r.z = rsqrtf(s.z * (1.f / 512.f) + 1e-6f);
        r.w = rsqrtf(s.w * (1.f / 512.f) + 1e-6f);
        *(float4*)&g_scale[m0 + l * 4] = r;
    }
}

// ---------------- K5p: A = gate*hid*scale -> [m][k] bf16 split ---------------
// 64m x 64d tile, float4 loads (8x fewer LDG, 4x MLP), pad-65 smem transpose,
// scale applied at store, full-128B bf16x2 row writes.
__global__ __launch_bounds__(256) void k5p()
{
    __shared__ float ts[64][65];
    const int m0 = blockIdx.x * 64, d0 = blockIdx.y * 64;
    const int tid = threadIdx.x;
#pragma unroll
    for (int k = 0; k < 4; k++) {
        const int idx = tid + k * 256;           // 0..1023
        const int row = idx >> 4, q = idx & 15;  // d-row, m-quad
        const size_t o = (size_t)(d0 + row) * MTOT + m0 + q * 4;
        const float4 h = *(const float4*)(g_hid + o);
        const float4 g = *(const float4*)(g_gate + o);
        ts[row][q * 4 + 0] = g.x * h.x;
        ts[row][q * 4 + 1] = g.y * h.y;
        ts[row][q * 4 + 2] = g.z * h.z;
        ts[row][q * 4 + 3] = g.w * h.w;
    }
    __syncthreads();
    const int dp = tid & 31, wid = tid >> 5;     // d-pair lane, warp = m-group
#pragma unroll
    for (int r = 0; r < 8; r++) {
        const int ml = wid * 8 + r;              // 0..63
        const float sc = g_scale[m0 + ml];
        const float v0 = ts[dp * 2][ml] * sc;
        const float v1 = ts[dp * 2 + 1][ml] * sc;
        const __nv_bfloat16 h0 = __float2bfloat16(v0);
        const __nv_bfloat16 h1 = __float2bfloat16(v1);
        const __nv_bfloat16 l0 = __float2bfloat16(v0 - __bfloat162float(h0));
        const __nv_bfloat16 l1 = __float2bfloat16(v1 - __bfloat162float(h1));
        const size_t o = (size_t)(m0 + ml) * 512 + d0 + dp * 2;
        __nv_bfloat162 hp; hp.x = h0; hp.y = h1;
        __nv_bfloat162 lp; lp.x = l0; lp.y = l1;
        *(__nv_bfloat162*)(g_ah + o) = hp;
        *(__nv_bfloat162*)(g_al + o) = lp;
    }
}

// ---------------- K5t: Y = A @ Wout + bout ----------------------------------
__global__ __launch_bounds__(256, 2) void k5t(const float* __restrict__ bout,
                                              float* __restrict__ out)
{
    extern __shared__ char smem[];
    const uint32_t sb = smem_u32(smem);
    const int tid = threadIdx.x, w = tid >> 5, l = tid & 31;
    const int n0 = blockIdx.x * 128;      // 0..511
    const int m0 = blockIdx.y * 128;

    float c[4][4][4];
    gemm_core(sb, g_ah, g_al, g_woth, g_wotl, m0, n0, c);

    // stage C as [m][n] (pad 132) for coalesced row writes
    float* sf = (float*)smem;
    {
        const int wm = (w & 1) * 64, wn = (w >> 1) * 32;
        const int mB = wm + (l >> 2), nB = wn + (l & 3) * 2;
#pragma unroll
        for (int mi = 0; mi < 4; mi++)
#pragma unroll
            for (int nj = 0; nj < 4; nj++) {
                const int m = mB + 16 * mi;
                const int n = nB + 8 * nj;
                sf[m * 132 + n]           = c[mi][nj][0];
                sf[m * 132 + n + 1]       = c[mi][nj][1];
                sf[(m + 8) * 132 + n]     = c[mi][nj][2];
                sf[(m + 8) * 132 + n + 1] = c[mi][nj][3];
            }
    }
    __syncthreads();

    const int ml = tid >> 1;
    const int nh = (tid & 1) * 64;
    const float* srow = sf + ml * 132 + nh;
    float* orow = out + (size_t)(m0 + ml) * 512 + n0 + nh;
    const float* brow = bout + n0 + nh;
#pragma unroll
    for (int i = 0; i < 16; i++) {
        float4 v = *(const float4*)(srow + i * 4);
        const float4 bo = *(const float4*)(brow + i * 4);
        *(float4*)(orow + i * 4) =
            make_float4(v.x + bo.x, v.y + bo.y, v.z + bo.z, v.w + bo.w);
    }
}

// ---------------- launch ----------------------------------------------------
extern "C" void kernel_launch(void* const* d_in, const int* in_sizes, int n_in,
                              void* d_out, int out_size)
{
    const float* x    = (const float*)d_in[0];
    const float* lb   = (const float*)d_in[1];
    const float* Win  = (const float*)d_in[2];
    const float* bin  = (const float*)d_in[3];
    const float* Wf   = (const float*)d_in[4];
    const float* bf   = (const float*)d_in[5];
    const float* th   = (const float*)d_in[6];
    const float* Wg   = (const float*)d_in[7];
    const float* bg   = (const float*)d_in[8];
    const float* Wout = (const float*)d_in[9];
    const float* bout = (const float*)d_in[10];
    float* out = (float*)d_out;

    cudaFuncSetAttribute(k1t, cudaFuncAttributeMaxDynamicSharedMemorySize, SMEM_BYTES);
    cudaFuncSetAttribute(k5t, cudaFuncAttributeMaxDynamicSharedMemorySize, SMEM_BYTES);
    const int scan_smem = 3 * 64 * 65 * 4;
    cudaFuncSetAttribute(k3_scan, cudaFuncAttributeMaxDynamicSharedMemorySize, scan_smem);

    k0x<<<16384, 256>>>(x);
    k0w<<<dim3(48, 16), dim3(32, 8)>>>(Win, Wf, Wg);
    k0wo<<<dim3(16, 16), dim3(32, 8)>>>(Wout);

    k1t<<<dim3(12, 256), 256, SMEM_BYTES>>>(bin, bf, bg, lb);

    k3_scan<<<dim3(DD, BB), 512, scan_smem>>>(th);
    k4_scale<<<256, 512>>>();
    k5p<<<dim3(MTOT / 64, DD / 64), 256>>>();

    k5t<<<dim3(4, 256), 256, SMEM_BYTES>>>(bout, out);
}